// round 12
// baseline (speedup 1.0000x reference)
#include <cuda_runtime.h>
#include <cuda_fp16.h>
#include <cstdint>

#define SEQ  512
#define NTHR 512
#define NCTA 128
#define OUTF 72

// ---- SMEM map (bytes) ----
#define OFF_W0  0        // Whh0 fp16 [256 n''][64 k] SW128 (32KB) — dead after prologue
#define OFF_W1  32768    // blk0=Wih1, blk1=Whh1 (+32768) (64KB) — dead after prologue
#define OFF_A0  98304    // h0 fp16 tile [16 m][64 cell], 2 buffers x 2KB
#define OFF_A1  102400   // h1 fp16 tile, 2 buffers x 2KB
#define OFF_XS  106496   // x chunk [32 s][16 m] f32 (2KB)
#define OFF_H1F 108544   // h1 last, fp32 [16][68]
#define SMEM_BYTES 112896

#define SW128(o) ((o) ^ (((o) >> 3) & 0x70))

__device__ __forceinline__ uint32_t smem_u32(const void* p) {
    uint32_t a;
    asm("{ .reg .u64 t; cvta.to.shared.u64 t, %1; cvt.u32.u64 %0, t; }" : "=r"(a) : "l"(p));
    return a;
}
__device__ __forceinline__ void ldsm4(uint32_t addr, uint32_t r[4]) {
    asm volatile("ldmatrix.sync.aligned.m8n8.x4.shared.b16 {%0,%1,%2,%3}, [%4];"
                 : "=r"(r[0]), "=r"(r[1]), "=r"(r[2]), "=r"(r[3]) : "r"(addr));
}
__device__ __forceinline__ void mma_f16(float d[4], const uint32_t a[4],
                                        uint32_t b0, uint32_t b1) {
    asm("mma.sync.aligned.m16n8k16.row.col.f32.f16.f16.f32 "
        "{%0,%1,%2,%3}, {%4,%5,%6,%7}, {%8,%9}, {%0,%1,%2,%3};"
        : "+f"(d[0]), "+f"(d[1]), "+f"(d[2]), "+f"(d[3])
        : "r"(a[0]), "r"(a[1]), "r"(a[2]), "r"(a[3]), "r"(b0), "r"(b1));
}
// in-place tanh on a packed f16x2
__device__ __forceinline__ __half2 th2(__half2 v) {
    uint32_t u = *reinterpret_cast<uint32_t*>(&v);
    asm("tanh.approx.f16x2 %0, %0;" : "+r"(u));
    return *reinterpret_cast<__half2*>(&u);
}

// Dual-row cell update. Inputs: fp32 gate pre-activations for rows 0/1
// (sigmoid gates pre-scaled by 0.5). c[2] kept in fp32. Returns h packed
// as half2 (lo = row0, hi = row1) — the exact format stored to the A tile.
__device__ __forceinline__ __half2 cellup2(float vi0, float vf0, float vg0, float vo0,
                                           float vi1, float vf1, float vg1, float vo1,
                                           float* c)
{
    __half2 ti2 = th2(__floats2half2_rn(vi0, vi1));
    __half2 tf2 = th2(__floats2half2_rn(vf0, vf1));
    __half2 tg2 = th2(__floats2half2_rn(vg0, vg1));
    __half2 to2 = th2(__floats2half2_rn(vo0, vo1));
    const __half2 h05 = __float2half2_rn(0.5f);
    __half2 i2 = __hfma2(ti2, h05, h05);
    __half2 f2 = __hfma2(tf2, h05, h05);
    __half2 o2 = __hfma2(to2, h05, h05);
    __half2 ig2 = __hmul2(i2, tg2);
    c[0] = fmaf(__low2float(f2),  c[0], __low2float(ig2));
    c[1] = fmaf(__high2float(f2), c[1], __high2float(ig2));
    __half2 tc2 = th2(__floats2half2_rn(c[0], c[1]));
    return __hmul2(o2, tc2);
}

__global__ __launch_bounds__(NTHR, 1)
void lstm_mma_kernel(const float* __restrict__ x,
                     const float* __restrict__ Wih0, const float* __restrict__ Whh0,
                     const float* __restrict__ bih0, const float* __restrict__ bhh0,
                     const float* __restrict__ Wih1, const float* __restrict__ Whh1,
                     const float* __restrict__ bih1, const float* __restrict__ bhh1,
                     const float* __restrict__ fcw,  const float* __restrict__ fcb,
                     float* __restrict__ out)
{
    extern __shared__ char smem[];
    const uint32_t sb = smem_u32(smem);
    const int tid = threadIdx.x, warp = tid >> 5, lane = tid & 31;
    const int r8 = lane & 7, mid = lane >> 3;

    // ldmatrix lane-address components (SW128, 128B rows) — proven R7-R11
    const uint32_t swz  = (uint32_t)(r8 << 4);
    const uint32_t aRow = (uint32_t)((r8 + ((mid & 1) << 3)) * 128);
    const uint32_t aK2  = (uint32_t)((mid & 2) << 3);
    const uint32_t bRow = (uint32_t)((r8 + ((mid & 2) << 2)) * 128);
    const uint32_t bK2  = (uint32_t)((mid & 1) << 4);

    // ---- weights -> SMEM, fp16, gate-pair-across-tiles layout ----
    // n'' = w*16 + gp*8 + c*2 + g2  ->  gate = gp*2+g2, cell = w*4+c
    for (int idx = tid; idx < 256 * 64; idx += NTHR) {
        int np = idx >> 6, k = idx & 63;
        int w = np >> 4, gp = (np >> 3) & 1, c = (np >> 1) & 3, g2 = np & 1;
        int row = (gp * 2 + g2) * 64 + (w * 4 + c);
        uint32_t off = SW128((uint32_t)(np * 128 + k * 2));
        *(__half*)(smem + OFF_W0 + off) = __float2half_rn(Whh0[row * 64 + k]);
    }
    for (int idx = tid; idx < 2 * 256 * 64; idx += NTHR) {
        int blk = idx >> 14, rem = idx & 16383;
        int np = rem >> 6, k = rem & 63;
        int w = np >> 4, gp = (np >> 3) & 1, c = (np >> 1) & 3, g2 = np & 1;
        int row = (gp * 2 + g2) * 64 + (w * 4 + c);
        float v = blk ? Whh1[row * 64 + k] : Wih1[row * 64 + k];
        uint32_t off = (uint32_t)(blk * 32768) + SW128((uint32_t)(np * 128 + k * 2));
        *(__half*)(smem + OFF_W1 + off) = __float2half_rn(v);
    }
    // zero h tiles (A0 x2 + A1 x2 = 8KB)
    for (int idx = tid; idx < 8192 / 4; idx += NTHR)
        ((uint32_t*)(smem + OFF_A0))[idx] = 0;

    // ---- per-lane assignment: ONE cell, TWO batch rows ----
    const int ct = warp * 4 + (lane & 3);      // this lane's cell
    const int m0 = lane >> 2, m1 = m0 + 8;     // this lane's batch rows
    float b0a[4], w0a[4], b1a[4];
#pragma unroll
    for (int g = 0; g < 4; ++g) {
        float sc = (g == 2) ? 1.0f : 0.5f;     // g-gate (tanh) unscaled
        b0a[g] = sc * (bih0[g * 64 + ct] + bhh0[g * 64 + ct]);
        w0a[g] = sc * Wih0[g * 64 + ct];
        b1a[g] = sc * (bih1[g * 64 + ct] + bhh1[g * 64 + ct]);
    }
    float c0[2] = {0.f, 0.f}, c1[2] = {0.f, 0.f};

    // loop-invariant h-store offsets (same swizzle nibble for m0 and m1)
    const uint32_t hoff0 = (uint32_t)(m0 * 128 + ct * 2) ^ (uint32_t)(m0 << 4);
    const uint32_t hoff1 = hoff0 + 1024;

    float* xs = (float*)(smem + OFF_XS);
    const int gRow = blockIdx.x * 16;

    // prologue x chunk [0..31]
    if (tid < 512) xs[tid] = x[(size_t)(gRow + (tid & 15)) * SEQ + (tid >> 4)];
    __syncthreads();

    // ---- preload weight fragments (warp owns 16 n''-cols at byte base warp*2048) ----
    uint32_t f0[4][4], f1[2][4][4];
#pragma unroll
    for (int kc = 0; kc < 4; ++kc) {
        uint32_t colB = ((uint32_t)(kc * 32) + bK2) ^ swz;
        ldsm4(sb + OFF_W0 + (uint32_t)(warp * 2048) + bRow + colB, f0[kc]);
#pragma unroll
        for (int blk = 0; blk < 2; ++blk)
            ldsm4(sb + OFF_W1 + (uint32_t)(blk * 32768 + warp * 2048) + bRow + colB,
                  f1[blk][kc]);
    }

    // ---- prologue: h0(0) = f(x(0)), zero recurrent term -> A0 buf0 ----
    {
        const float xi0 = xs[m0], xi1 = xs[m1];
        __half2 h2 = cellup2(
            fmaf(w0a[0], xi0, b0a[0]), fmaf(w0a[1], xi0, b0a[1]),
            fmaf(w0a[2], xi0, b0a[2]), fmaf(w0a[3], xi0, b0a[3]),
            fmaf(w0a[0], xi1, b0a[0]), fmaf(w0a[1], xi1, b0a[1]),
            fmaf(w0a[2], xi1, b0a[2]), fmaf(w0a[3], xi1, b0a[3]), c0);
        *(__half*)(smem + OFF_A0 + hoff0) = __low2half(h2);
        *(__half*)(smem + OFF_A0 + hoff1) = __high2half(h2);
    }
    __syncthreads();

    // ================= main loop: ONE barrier per step =================
#pragma unroll 2
    for (int s = 0; s < SEQ; ++s) {
        if (((s + 1) & 31) == 0 && (s + 1) < SEQ) {   // refill x for chunk s+1..s+32
            if (tid < 512)
                xs[tid] = x[(size_t)(gRow + (tid & 15)) * SEQ + (s + 1) + (tid >> 4)];
            __syncthreads();
        }
        const int rb = s & 1;
        const uint32_t A0r = sb + OFF_A0 + (uint32_t)(rb * 2048);          // h0(s)
        const uint32_t A1r = sb + OFF_A1 + (uint32_t)(rb * 2048);          // h1(s-1)
        const uint32_t A0w = sb + OFF_A0 + (uint32_t)((1 - rb) * 2048);    // h0(s+1)
        const uint32_t A1w = sb + OFF_A1 + (uint32_t)((1 - rb) * 2048);    // h1(s)

        // ---- merged MMA block: L1(s) [split accum] + L0(s+1) [split accum] ----
        float d0a[2][4], d0b[2][4], d1a[2][4], d1b[2][4];
#pragma unroll
        for (int t = 0; t < 2; ++t)
#pragma unroll
            for (int q = 0; q < 4; ++q) {
                d0a[t][q] = 0.f; d0b[t][q] = 0.f;
                d1a[t][q] = 0.f; d1b[t][q] = 0.f;
            }
#pragma unroll
        for (int kc = 0; kc < 4; ++kc) {
            uint32_t colA = (((uint32_t)(kc * 32)) + aK2) ^ swz;
            uint32_t a[4], b[4];
            ldsm4(A0r + aRow + colA, a);            // h0(s)
            ldsm4(A1r + aRow + colA, b);            // h1(s-1)
            float (*dd0)[4] = (kc & 1) ? d0b : d0a; // 2-deep chains
            mma_f16(dd0[0], a, f0[kc][0], f0[kc][1]);        // h0 @ Whh0  (s+1)
            mma_f16(dd0[1], a, f0[kc][2], f0[kc][3]);
            mma_f16(d1a[0], a, f1[0][kc][0], f1[0][kc][1]);  // h0 @ Wih1
            mma_f16(d1a[1], a, f1[0][kc][2], f1[0][kc][3]);
            mma_f16(d1b[0], b, f1[1][kc][0], f1[1][kc][1]);  // h1 @ Whh1
            mma_f16(d1b[1], b, f1[1][kc][2], f1[1][kc][3]);
        }

        // ---- epilogue L0(s+1): d0a+d0b, fed by x(s+1) ----
        {
            const int sn = (s + 1 < SEQ) ? (s + 1) : s;
            const float xi0 = xs[(sn & 31) * 16 + m0];
            const float xi1 = xs[(sn & 31) * 16 + m1];
            __half2 h2 = cellup2(
                fmaf(w0a[0], xi0, b0a[0]) + (d0a[0][0] + d0b[0][0]) * 0.5f,
                fmaf(w0a[1], xi0, b0a[1]) + (d0a[0][1] + d0b[0][1]) * 0.5f,
                fmaf(w0a[2], xi0, b0a[2]) + (d0a[1][0] + d0b[1][0]),
                fmaf(w0a[3], xi0, b0a[3]) + (d0a[1][1] + d0b[1][1]) * 0.5f,
                fmaf(w0a[0], xi1, b0a[0]) + (d0a[0][2] + d0b[0][2]) * 0.5f,
                fmaf(w0a[1], xi1, b0a[1]) + (d0a[0][3] + d0b[0][3]) * 0.5f,
                fmaf(w0a[2], xi1, b0a[2]) + (d0a[1][2] + d0b[1][2]),
                fmaf(w0a[3], xi1, b0a[3]) + (d0a[1][3] + d0b[1][3]) * 0.5f, c0);
            *(__half*)(smem + (A0w - sb) + hoff0) = __low2half(h2);
            *(__half*)(smem + (A0w - sb) + hoff1) = __high2half(h2);
        }
        // ---- epilogue L1(s): gates = d1a + d1b ----
        {
            __half2 h2 = cellup2(
                fmaf(d1a[0][0] + d1b[0][0], 0.5f, b1a[0]),
                fmaf(d1a[0][1] + d1b[0][1], 0.5f, b1a[1]),
                (d1a[1][0] + d1b[1][0]) + b1a[2],
                fmaf(d1a[1][1] + d1b[1][1], 0.5f, b1a[3]),
                fmaf(d1a[0][2] + d1b[0][2], 0.5f, b1a[0]),
                fmaf(d1a[0][3] + d1b[0][3], 0.5f, b1a[1]),
                (d1a[1][2] + d1b[1][2]) + b1a[2],
                fmaf(d1a[1][3] + d1b[1][3], 0.5f, b1a[3]), c1);
            *(__half*)(smem + (A1w - sb) + hoff0) = __low2half(h2);
            *(__half*)(smem + (A1w - sb) + hoff1) = __high2half(h2);
            if (s == SEQ - 1) {
                ((float*)(smem + OFF_H1F))[m0 * 68 + ct] = __low2float(h2);
                ((float*)(smem + OFF_H1F))[m1 * 68 + ct] = __high2float(h2);
            }
        }
        __syncthreads();   // the one barrier: stores(s) visible before reads(s+1)
    }

    // ================= final FC: out = h1(S-1) @ fcw^T + fcb =================
    const float* h1f = (const float*)(smem + OFF_H1F);
    for (int idx = tid; idx < 16 * OUTF; idx += NTHR) {
        int r = idx / OUTF, o = idx - r * OUTF;
        float acc = fcb[o];
#pragma unroll 16
        for (int k = 0; k < 64; ++k)
            acc = fmaf(h1f[r * 68 + k], fcw[o * 64 + k], acc);
        out[(gRow + r) * OUTF + o] = acc;
    }
}

extern "C" void kernel_launch(void* const* d_in, const int* in_sizes, int n_in,
                              void* d_out, int out_size)
{
    (void)in_sizes; (void)n_in; (void)out_size;
    cudaFuncSetAttribute(lstm_mma_kernel,
                         cudaFuncAttributeMaxDynamicSharedMemorySize, SMEM_BYTES);
    lstm_mma_kernel<<<NCTA, NTHR, SMEM_BYTES>>>(
        (const float*)d_in[0],  (const float*)d_in[1],  (const float*)d_in[2],
        (const float*)d_in[3],  (const float*)d_in[4],  (const float*)d_in[5],
        (const float*)d_in[6],  (const float*)d_in[7],  (const float*)d_in[8],
        (const float*)d_in[9],  (const float*)d_in[10], (float*)d_out);
}

// round 13
// speedup vs baseline: 1.0273x; 1.0273x over previous
#include <cuda_runtime.h>
#include <cuda_fp16.h>
#include <cstdint>

#define SEQ  512
#define NTHR 512
#define NCTA 128
#define OUTF 72

// ---- SMEM map (bytes) ----
#define OFF_W0  0        // Whh0 fp16 [256 n''][64 k] SW128 (32KB) — dead after preload
#define OFF_W1  32768    // blk0=Wih1, blk1=Whh1 (+32768) (64KB) — dead after preload
#define OFF_H0  98304    // h0 fp16 tile [16 m][64 cell], RING of 4 x 2KB
#define OFF_H1  106496   // h1 fp16 tile, 2 buffers x 2KB
#define OFF_XS  110592   // x chunk [32 s][16 m] f32 (2KB)
#define OFF_H1F 112640   // h1 last, fp32 [16][68] (4352B)
#define OFF_MB  116992   // mbarriers: full[4] then empty[4], 8B each
#define SMEM_BYTES 117056

#define SW128(o) ((o) ^ (((o) >> 3) & 0x70))

__device__ __forceinline__ uint32_t smem_u32(const void* p) {
    uint32_t a;
    asm("{ .reg .u64 t; cvta.to.shared.u64 t, %1; cvt.u32.u64 %0, t; }" : "=r"(a) : "l"(p));
    return a;
}
__device__ __forceinline__ void ldsm4(uint32_t addr, uint32_t r[4]) {
    asm volatile("ldmatrix.sync.aligned.m8n8.x4.shared.b16 {%0,%1,%2,%3}, [%4];"
                 : "=r"(r[0]), "=r"(r[1]), "=r"(r[2]), "=r"(r[3]) : "r"(addr));
}
__device__ __forceinline__ void mma_f16(float d[4], const uint32_t a[4],
                                        uint32_t b0, uint32_t b1) {
    asm("mma.sync.aligned.m16n8k16.row.col.f32.f16.f16.f32 "
        "{%0,%1,%2,%3}, {%4,%5,%6,%7}, {%8,%9}, {%0,%1,%2,%3};"
        : "+f"(d[0]), "+f"(d[1]), "+f"(d[2]), "+f"(d[3])
        : "r"(a[0]), "r"(a[1]), "r"(a[2]), "r"(a[3]), "r"(b0), "r"(b1));
}
__device__ __forceinline__ float tanha(float x) {
    float y; asm("tanh.approx.f32 %0, %1;" : "=f"(y) : "f"(x)); return y;
}
#define BARSYNC(id, cnt) asm volatile("bar.sync %0, %1;" :: "r"(id), "r"(cnt) : "memory")
#define MBAR_INIT(mb, c) \
    asm volatile("mbarrier.init.shared.b64 [%0], %1;" :: "r"((uint32_t)(mb)), "r"((uint32_t)(c)) : "memory")
#define MBAR_ARRIVE(mb) \
    asm volatile("mbarrier.arrive.shared.b64 _, [%0];" :: "r"((uint32_t)(mb)) : "memory")
#define MBAR_WAIT(mb, par) do {                                                   \
    uint32_t _m = (uint32_t)(mb), _p = (uint32_t)(par), _d;                       \
    asm volatile("{ .reg .pred p; mbarrier.try_wait.parity.acquire.cta.shared::cta.b64 p, [%1], %2;" \
                 " selp.b32 %0, 1, 0, p; }" : "=r"(_d) : "r"(_m), "r"(_p) : "memory"); \
    if (!_d) {                                                                    \
        asm volatile("{ .reg .pred P1; WL_%=:"                                    \
            " mbarrier.try_wait.parity.acquire.cta.shared::cta.b64 P1, [%0], %1, 0x989680;" \
            " @P1 bra.uni WD_%=; bra.uni WL_%=; WD_%=: }"                         \
            :: "r"(_m), "r"(_p) : "memory");                                      \
    }                                                                             \
} while (0)

// f32 cell update (R11-proven). Sigmoid-gate inputs pre-scaled by 0.5.
__device__ __forceinline__ float cellup(float gi, float gf, float gg, float go,
                                        const float b[4],
                                        float wx0, float wx1, float wx2, float wx3,
                                        float& c)
{
    float vi = fmaf(gi, 0.5f, b[0] + wx0);
    float vf = fmaf(gf, 0.5f, b[1] + wx1);
    float vg = gg + b[2] + wx2;
    float vo = fmaf(go, 0.5f, b[3] + wx3);
    float ii = fmaf(tanha(vi), 0.5f, 0.5f);
    float ff = fmaf(tanha(vf), 0.5f, 0.5f);
    float tg = tanha(vg);
    float oo = fmaf(tanha(vo), 0.5f, 0.5f);
    c = fmaf(ff, c, ii * tg);
    return oo * tanha(c);
}

__global__ __launch_bounds__(NTHR, 1)
void lstm_mma_kernel(const float* __restrict__ x,
                     const float* __restrict__ Wih0, const float* __restrict__ Whh0,
                     const float* __restrict__ bih0, const float* __restrict__ bhh0,
                     const float* __restrict__ Wih1, const float* __restrict__ Whh1,
                     const float* __restrict__ bih1, const float* __restrict__ bhh1,
                     const float* __restrict__ fcw,  const float* __restrict__ fcb,
                     float* __restrict__ out)
{
    extern __shared__ char smem[];
    const uint32_t sb = smem_u32(smem);
    const int tid = threadIdx.x, warp = tid >> 5, lane = tid & 31;
    const int r8 = lane & 7, mid = lane >> 3;

    // ldmatrix lane-address components (SW128, 128B rows) — proven R7-R12
    const uint32_t swz  = (uint32_t)(r8 << 4);
    const uint32_t aRow = (uint32_t)((r8 + ((mid & 1) << 3)) * 128);
    const uint32_t aK2  = (uint32_t)((mid & 2) << 3);
    const uint32_t bRow = (uint32_t)((r8 + ((mid & 2) << 2)) * 128);
    const uint32_t bK2  = (uint32_t)((mid & 1) << 4);

    // ---- weights -> SMEM, fp16 ----
    // n'' = w*32 + pair*16 + gp*8 + c*2 + g2 : gate = gp*2+g2, cell = w*8+pair*4+c
    for (int idx = tid; idx < 256 * 64; idx += NTHR) {
        int np = idx >> 6, k = idx & 63;
        int gate = ((np >> 3) & 1) * 2 + (np & 1);
        int cell = (np >> 5) * 8 + ((np >> 4) & 1) * 4 + ((np >> 1) & 3);
        uint32_t off = SW128((uint32_t)(np * 128 + k * 2));
        *(__half*)(smem + OFF_W0 + off) = __float2half_rn(Whh0[(gate * 64 + cell) * 64 + k]);
    }
    for (int idx = tid; idx < 2 * 256 * 64; idx += NTHR) {
        int blk = idx >> 14, rem = idx & 16383;
        int np = rem >> 6, k = rem & 63;
        int gate = ((np >> 3) & 1) * 2 + (np & 1);
        int cell = (np >> 5) * 8 + ((np >> 4) & 1) * 4 + ((np >> 1) & 3);
        float v = blk ? Whh1[(gate * 64 + cell) * 64 + k] : Wih1[(gate * 64 + cell) * 64 + k];
        uint32_t off = (uint32_t)(blk * 32768) + SW128((uint32_t)(np * 128 + k * 2));
        *(__half*)(smem + OFF_W1 + off) = __float2half_rn(v);
    }
    // zero h tiles (H0 ring 8KB + H1 4KB)
    for (int idx = tid; idx < 12288 / 4; idx += NTHR)
        ((uint32_t*)(smem + OFF_H0))[idx] = 0;
    if (tid == 0) {
#pragma unroll
        for (int sl = 0; sl < 4; ++sl) {
            MBAR_INIT(sb + OFF_MB + sl * 8, 256);        // full[sl]
            MBAR_INIT(sb + OFF_MB + 32 + sl * 8, 256);   // empty[sl]
        }
    }

    const int m0 = lane >> 2, m1 = m0 + 8;
    const int gRow = blockIdx.x * 16;
    float* xs = (float*)(smem + OFF_XS);
    __syncthreads();

    if (warp < 8) {
        // ================= GROUP A: layer 0 =================
        int ct[2];
        float b0a[2][4], w0a[2][4];
        uint32_t hoff[2];
#pragma unroll
        for (int p = 0; p < 2; ++p) {
            ct[p] = warp * 8 + p * 4 + (lane & 3);
#pragma unroll
            for (int g = 0; g < 4; ++g) {
                float sc = (g == 2) ? 1.0f : 0.5f;
                b0a[p][g] = sc * (bih0[g * 64 + ct[p]] + bhh0[g * 64 + ct[p]]);
                w0a[p][g] = sc * Wih0[g * 64 + ct[p]];
            }
            hoff[p] = (uint32_t)(m0 * 128 + ct[p] * 2) ^ (uint32_t)(m0 << 4);
        }
        float c0[2][2] = {{0.f, 0.f}, {0.f, 0.f}};

        // preload Whh0 fragments: 2 tile-pairs, 4 kc
        uint32_t f0[2][4][4];
#pragma unroll
        for (int kc = 0; kc < 4; ++kc) {
            uint32_t colB = ((uint32_t)(kc * 32) + bK2) ^ swz;
#pragma unroll
            for (int p = 0; p < 2; ++p)
                ldsm4(sb + OFF_W0 + (uint32_t)(warp * 4096 + p * 2048) + bRow + colB, f0[p][kc]);
        }

        for (int t = 0; t < SEQ; ++t) {
            if ((t & 31) == 0) {   // refill x chunk for steps t..t+31
                for (int q = tid; q < 512; q += 256)
                    xs[q] = x[(size_t)(gRow + (q & 15)) * SEQ + t + (q >> 4)];
                BARSYNC(1, 256);
            }
            const uint32_t A0r = sb + OFF_H0 + (uint32_t)(((t - 1) & 3) * 2048);  // h0(t-1)
            const uint32_t A0w = sb + OFF_H0 + (uint32_t)((t & 3) * 2048);        // h0(t)

            float d[2][2][4];
#pragma unroll
            for (int p = 0; p < 2; ++p)
#pragma unroll
                for (int u = 0; u < 2; ++u)
                    d[p][u][0] = d[p][u][1] = d[p][u][2] = d[p][u][3] = 0.f;
#pragma unroll
            for (int kc = 0; kc < 4; ++kc) {
                uint32_t a[4];
                ldsm4(A0r + aRow + ((((uint32_t)(kc * 32)) + aK2) ^ swz), a);
#pragma unroll
                for (int p = 0; p < 2; ++p) {
                    mma_f16(d[p][0], a, f0[p][kc][0], f0[p][kc][1]);
                    mma_f16(d[p][1], a, f0[p][kc][2], f0[p][kc][3]);
                }
            }
            // epilogue: h0(t) (in registers)
            const float xi0 = xs[(t & 31) * 16 + m0];
            const float xi1 = xs[(t & 31) * 16 + m1];
            __half hv[2][2];
#pragma unroll
            for (int p = 0; p < 2; ++p) {
                hv[p][0] = __float2half_rn(cellup(d[p][0][0], d[p][0][1], d[p][1][0], d[p][1][1],
                    b0a[p], w0a[p][0]*xi0, w0a[p][1]*xi0, w0a[p][2]*xi0, w0a[p][3]*xi0, c0[p][0]));
                hv[p][1] = __float2half_rn(cellup(d[p][0][2], d[p][0][3], d[p][1][2], d[p][1][3],
                    b0a[p], w0a[p][0]*xi1, w0a[p][1]*xi1, w0a[p][2]*xi1, w0a[p][3]*xi1, c0[p][1]));
            }
            // ring backpressure: B must have consumed h0(t-4) from this slot
            if (t >= 4) MBAR_WAIT(sb + OFF_MB + 32 + (t & 3) * 8, ((t >> 2) - 1) & 1);
#pragma unroll
            for (int p = 0; p < 2; ++p) {
                *(__half*)(smem + (A0w - sb) + hoff[p])        = hv[p][0];
                *(__half*)(smem + (A0w - sb) + hoff[p] + 1024) = hv[p][1];
            }
            MBAR_ARRIVE(sb + OFF_MB + (t & 3) * 8);   // full[t&3] (release)
            BARSYNC(1, 256);                           // A-internal: stores before next ldsm
        }
    } else {
        // ================= GROUP B: layer 1 =================
        const int warpB = warp - 8;
        int ct[2];
        float b1a[2][4];
        uint32_t hoff[2];
#pragma unroll
        for (int p = 0; p < 2; ++p) {
            ct[p] = warpB * 8 + p * 4 + (lane & 3);
#pragma unroll
            for (int g = 0; g < 4; ++g) {
                float sc = (g == 2) ? 1.0f : 0.5f;
                b1a[p][g] = sc * (bih1[g * 64 + ct[p]] + bhh1[g * 64 + ct[p]]);
            }
            hoff[p] = (uint32_t)(m0 * 128 + ct[p] * 2) ^ (uint32_t)(m0 << 4);
        }
        float c1[2][2] = {{0.f, 0.f}, {0.f, 0.f}};

        // preload W1 fragments: 2 blocks x 2 tile-pairs x 4 kc
        uint32_t f1[2][2][4][4];
#pragma unroll
        for (int kc = 0; kc < 4; ++kc) {
            uint32_t colB = ((uint32_t)(kc * 32) + bK2) ^ swz;
#pragma unroll
            for (int blk = 0; blk < 2; ++blk)
#pragma unroll
                for (int p = 0; p < 2; ++p)
                    ldsm4(sb + OFF_W1 + (uint32_t)(blk * 32768 + warpB * 4096 + p * 2048)
                          + bRow + colB, f1[blk][p][kc]);
        }

        for (int t = 0; t < SEQ; ++t) {
            const uint32_t H0s = sb + OFF_H0 + (uint32_t)((t & 3) * 2048);        // h0(t)
            const uint32_t A1r = sb + OFF_H1 + (uint32_t)((((t - 1) & 1)) * 2048);// h1(t-1)
            const uint32_t A1w = sb + OFF_H1 + (uint32_t)((t & 1) * 2048);        // h1(t)

            MBAR_WAIT(sb + OFF_MB + (t & 3) * 8, (t >> 2) & 1);   // full[t&3] (acquire)
            uint32_t a0f[4][4];
#pragma unroll
            for (int kc = 0; kc < 4; ++kc)
                ldsm4(H0s + aRow + ((((uint32_t)(kc * 32)) + aK2) ^ swz), a0f[kc]);
            MBAR_ARRIVE(sb + OFF_MB + 32 + (t & 3) * 8);          // empty[t&3]

            float da[2][2][4], db[2][2][4];
#pragma unroll
            for (int p = 0; p < 2; ++p)
#pragma unroll
                for (int u = 0; u < 2; ++u) {
                    da[p][u][0] = da[p][u][1] = da[p][u][2] = da[p][u][3] = 0.f;
                    db[p][u][0] = db[p][u][1] = db[p][u][2] = db[p][u][3] = 0.f;
                }
#pragma unroll
            for (int kc = 0; kc < 4; ++kc) {
                uint32_t b[4];
                ldsm4(A1r + aRow + ((((uint32_t)(kc * 32)) + aK2) ^ swz), b);
#pragma unroll
                for (int p = 0; p < 2; ++p) {
                    mma_f16(da[p][0], a0f[kc], f1[0][p][kc][0], f1[0][p][kc][1]);
                    mma_f16(da[p][1], a0f[kc], f1[0][p][kc][2], f1[0][p][kc][3]);
                    mma_f16(db[p][0], b,       f1[1][p][kc][0], f1[1][p][kc][1]);
                    mma_f16(db[p][1], b,       f1[1][p][kc][2], f1[1][p][kc][3]);
                }
            }
            // epilogue: h1(t)
#pragma unroll
            for (int p = 0; p < 2; ++p) {
                float h0v = cellup(da[p][0][0] + db[p][0][0], da[p][0][1] + db[p][0][1],
                                   da[p][1][0] + db[p][1][0], da[p][1][1] + db[p][1][1],
                                   b1a[p], 0.f, 0.f, 0.f, 0.f, c1[p][0]);
                float h1v = cellup(da[p][0][2] + db[p][0][2], da[p][0][3] + db[p][0][3],
                                   da[p][1][2] + db[p][1][2], da[p][1][3] + db[p][1][3],
                                   b1a[p], 0.f, 0.f, 0.f, 0.f, c1[p][1]);
                *(__half*)(smem + (A1w - sb) + hoff[p])        = __float2half_rn(h0v);
                *(__half*)(smem + (A1w - sb) + hoff[p] + 1024) = __float2half_rn(h1v);
                if (t == SEQ - 1) {
                    ((float*)(smem + OFF_H1F))[m0 * 68 + ct[p]] = h0v;
                    ((float*)(smem + OFF_H1F))[m1 * 68 + ct[p]] = h1v;
                }
            }
            BARSYNC(2, 256);   // B-internal: h1 stores before next read
        }

        // ---- final FC by group B: out = h1(S-1) @ fcw^T + fcb ----
        const float* h1f = (const float*)(smem + OFF_H1F);
        for (int idx = tid - 256; idx < 16 * OUTF; idx += 256) {
            int r = idx / OUTF, o = idx - r * OUTF;
            float acc = fcb[o];
#pragma unroll 16
            for (int k = 0; k < 64; ++k)
                acc = fmaf(h1f[r * 68 + k], fcw[o * 64 + k], acc);
            out[(gRow + r) * OUTF + o] = acc;
        }
    }
}

extern "C" void kernel_launch(void* const* d_in, const int* in_sizes, int n_in,
                              void* d_out, int out_size)
{
    (void)in_sizes; (void)n_in; (void)out_size;
    cudaFuncSetAttribute(lstm_mma_kernel,
                         cudaFuncAttributeMaxDynamicSharedMemorySize, SMEM_BYTES);
    lstm_mma_kernel<<<NCTA, NTHR, SMEM_BYTES>>>(
        (const float*)d_in[0],  (const float*)d_in[1],  (const float*)d_in[2],
        (const float*)d_in[3],  (const float*)d_in[4],  (const float*)d_in[5],
        (const float*)d_in[6],  (const float*)d_in[7],  (const float*)d_in[8],
        (const float*)d_in[9],  (const float*)d_in[10], (float*)d_out);
}

// round 14
// speedup vs baseline: 1.1543x; 1.1236x over previous
#include <cuda_runtime.h>
#include <cuda_fp16.h>
#include <cstdint>

#define SEQ  512
#define NTHR 256
#define NCTA 128
#define OUTF 72

// ---- SMEM map (bytes) ----
#define OFF_W0  0        // Whh0 fp16 [256 n''][64 k] SW128 (32KB) — dead after preload
#define OFF_W1  32768    // blk0=Wih1, blk1=Whh1 (+32768) (64KB) — dead after preload
#define OFF_A0  98304    // h0 fp16 tile [16 m][64 cell], 2 buffers x 2KB
#define OFF_A1  102400   // h1 fp16 tile, 2 buffers x 2KB
#define OFF_XS  106496   // x chunk [32 s][16 m] f32 (2KB)
#define OFF_H1F 108544   // h1 last, fp32 [16][68]
#define SMEM_BYTES 112896

#define SW128(o) ((o) ^ (((o) >> 3) & 0x70))

__device__ __forceinline__ uint32_t smem_u32(const void* p) {
    uint32_t a;
    asm("{ .reg .u64 t; cvta.to.shared.u64 t, %1; cvt.u32.u64 %0, t; }" : "=r"(a) : "l"(p));
    return a;
}
__device__ __forceinline__ void ldsm4(uint32_t addr, uint32_t r[4]) {
    asm volatile("ldmatrix.sync.aligned.m8n8.x4.shared.b16 {%0,%1,%2,%3}, [%4];"
                 : "=r"(r[0]), "=r"(r[1]), "=r"(r[2]), "=r"(r[3]) : "r"(addr));
}
__device__ __forceinline__ void mma_f16(float d[4], const uint32_t a[4],
                                        uint32_t b0, uint32_t b1) {
    asm("mma.sync.aligned.m16n8k16.row.col.f32.f16.f16.f32 "
        "{%0,%1,%2,%3}, {%4,%5,%6,%7}, {%8,%9}, {%0,%1,%2,%3};"
        : "+f"(d[0]), "+f"(d[1]), "+f"(d[2]), "+f"(d[3])
        : "r"(a[0]), "r"(a[1]), "r"(a[2]), "r"(a[3]), "r"(b0), "r"(b1));
}
__device__ __forceinline__ float tanha(float x) {
    float y; asm("tanh.approx.f32 %0, %1;" : "=f"(y) : "f"(x)); return y;
}

// Cell update. All sigmoid-gate inputs (gi,gf,go, their b and wx) arrive
// pre-scaled by 0.5 — including the MMA outputs (weights pre-scaled in SMEM).
__device__ __forceinline__ float cellup(float gi, float gf, float gg, float go,
                                        const float b[4],
                                        float wx0, float wx1, float wx2, float wx3,
                                        float& c)
{
    float vi = gi + b[0] + wx0;
    float vf = gf + b[1] + wx1;
    float vg = gg + b[2] + wx2;
    float vo = go + b[3] + wx3;
    float ii = fmaf(tanha(vi), 0.5f, 0.5f);
    float ff = fmaf(tanha(vf), 0.5f, 0.5f);
    float tg = tanha(vg);
    float oo = fmaf(tanha(vo), 0.5f, 0.5f);
    c = fmaf(ff, c, ii * tg);
    return oo * tanha(c);
}

__global__ __launch_bounds__(NTHR, 1)
void lstm_mma_kernel(const float* __restrict__ x,
                     const float* __restrict__ Wih0, const float* __restrict__ Whh0,
                     const float* __restrict__ bih0, const float* __restrict__ bhh0,
                     const float* __restrict__ Wih1, const float* __restrict__ Whh1,
                     const float* __restrict__ bih1, const float* __restrict__ bhh1,
                     const float* __restrict__ fcw,  const float* __restrict__ fcb,
                     float* __restrict__ out)
{
    extern __shared__ char smem[];
    const uint32_t sb = smem_u32(smem);
    const int tid = threadIdx.x, warp = tid >> 5, lane = tid & 31;
    const int r8 = lane & 7, mid = lane >> 3;

    // ldmatrix lane-address components (SW128, 128B rows) — proven R7-R13
    const uint32_t swz  = (uint32_t)(r8 << 4);
    const uint32_t aRow = (uint32_t)((r8 + ((mid & 1) << 3)) * 128);
    const uint32_t aK2  = (uint32_t)((mid & 2) << 3);
    const uint32_t bRow = (uint32_t)((r8 + ((mid & 2) << 2)) * 128);
    const uint32_t bK2  = (uint32_t)((mid & 1) << 4);

    // ---- weights -> SMEM, fp16, SIGMOID ROWS PRE-SCALED by 0.5 (exact) ----
    // n'' = w*32 + pair*16 + gp*8 + c*2 + g2 : gate = gp*2+g2, cell = w*8+pair*4+c
    for (int idx = tid; idx < 256 * 64; idx += NTHR) {
        int np = idx >> 6, k = idx & 63;
        int gate = ((np >> 3) & 1) * 2 + (np & 1);
        int cell = (np >> 5) * 8 + ((np >> 4) & 1) * 4 + ((np >> 1) & 3);
        float sc = (gate == 2) ? 1.0f : 0.5f;
        uint32_t off = SW128((uint32_t)(np * 128 + k * 2));
        *(__half*)(smem + OFF_W0 + off) =
            __float2half_rn(sc * Whh0[(gate * 64 + cell) * 64 + k]);
    }
    for (int idx = tid; idx < 2 * 256 * 64; idx += NTHR) {
        int blk = idx >> 14, rem = idx & 16383;
        int np = rem >> 6, k = rem & 63;
        int gate = ((np >> 3) & 1) * 2 + (np & 1);
        int cell = (np >> 5) * 8 + ((np >> 4) & 1) * 4 + ((np >> 1) & 3);
        float sc = (gate == 2) ? 1.0f : 0.5f;
        float v = blk ? Whh1[(gate * 64 + cell) * 64 + k] : Wih1[(gate * 64 + cell) * 64 + k];
        uint32_t off = (uint32_t)(blk * 32768) + SW128((uint32_t)(np * 128 + k * 2));
        *(__half*)(smem + OFF_W1 + off) = __float2half_rn(sc * v);
    }
    // zero h tiles (A0 x2 + A1 x2 = 8KB)
    for (int idx = tid; idx < 8192 / 4; idx += NTHR)
        ((uint32_t*)(smem + OFF_A0))[idx] = 0;

    // ---- per-lane assignment: 2 cells (one per tile-pair), 2 batch rows ----
    const int m0 = lane >> 2, m1 = m0 + 8;
    int ct[2];
    float b0a[2][4], w0a[2][4], b1a[2][4];
    uint32_t hoff[2];
#pragma unroll
    for (int p = 0; p < 2; ++p) {
        ct[p] = warp * 8 + p * 4 + (lane & 3);
#pragma unroll
        for (int g = 0; g < 4; ++g) {
            float sc = (g == 2) ? 1.0f : 0.5f;
            b0a[p][g] = sc * (bih0[g * 64 + ct[p]] + bhh0[g * 64 + ct[p]]);
            w0a[p][g] = sc * Wih0[g * 64 + ct[p]];
            b1a[p][g] = sc * (bih1[g * 64 + ct[p]] + bhh1[g * 64 + ct[p]]);
        }
        hoff[p] = (uint32_t)(m0 * 128 + ct[p] * 2) ^ (uint32_t)(m0 << 4);
    }
    float c0[2][2] = {{0.f, 0.f}, {0.f, 0.f}};
    float c1[2][2] = {{0.f, 0.f}, {0.f, 0.f}};

    float* xs = (float*)(smem + OFF_XS);
    const int gRow = blockIdx.x * 16;

    // prologue x chunk [0..31]
    for (int q = tid; q < 512; q += NTHR)
        xs[q] = x[(size_t)(gRow + (q & 15)) * SEQ + (q >> 4)];
    __syncthreads();

    // ---- preload weight fragments (warp owns 32 n''-cols at byte base warp*4096) ----
    uint32_t f0[2][4][4], f1a[2][4][4], f1b[2][4][4];
#pragma unroll
    for (int kc = 0; kc < 4; ++kc) {
        uint32_t colB = ((uint32_t)(kc * 32) + bK2) ^ swz;
#pragma unroll
        for (int p = 0; p < 2; ++p) {
            uint32_t base = (uint32_t)(warp * 4096 + p * 2048) + bRow + colB;
            ldsm4(sb + OFF_W0 + base, f0[p][kc]);
            ldsm4(sb + OFF_W1 + base, f1a[p][kc]);
            ldsm4(sb + OFF_W1 + 32768 + base, f1b[p][kc]);
        }
    }

    // ---- prologue: h0(0) = f(x(0)), zero recurrent term -> A0 buf0 ----
    {
        const float xi0 = xs[m0], xi1 = xs[m1];
#pragma unroll
        for (int p = 0; p < 2; ++p) {
            float h;
            h = cellup(0.f, 0.f, 0.f, 0.f, b0a[p],
                       w0a[p][0]*xi0, w0a[p][1]*xi0, w0a[p][2]*xi0, w0a[p][3]*xi0, c0[p][0]);
            *(__half*)(smem + OFF_A0 + hoff[p]) = __float2half_rn(h);
            h = cellup(0.f, 0.f, 0.f, 0.f, b0a[p],
                       w0a[p][0]*xi1, w0a[p][1]*xi1, w0a[p][2]*xi1, w0a[p][3]*xi1, c0[p][1]);
            *(__half*)(smem + OFF_A0 + hoff[p] + 1024) = __float2half_rn(h);
        }
    }
    __syncthreads();

    // ================= main loop: ONE barrier per step =================
#pragma unroll 2
    for (int s = 0; s < SEQ; ++s) {
        if (((s + 1) & 31) == 0 && (s + 1) < SEQ) {   // refill x for chunk s+1..s+32
            for (int q = tid; q < 512; q += NTHR)
                xs[q] = x[(size_t)(gRow + (q & 15)) * SEQ + (s + 1) + (q >> 4)];
            __syncthreads();
        }
        const int rb = s & 1;
        const uint32_t A0r = sb + OFF_A0 + (uint32_t)(rb * 2048);          // h0(s)
        const uint32_t A1r = sb + OFF_A1 + (uint32_t)(rb * 2048);          // h1(s-1)
        const uint32_t A0w = sb + OFF_A0 + (uint32_t)((1 - rb) * 2048);    // h0(s+1)
        const uint32_t A1w = sb + OFF_A1 + (uint32_t)((1 - rb) * 2048);    // h1(s)

        // ---- A-fragment loads (h0(s), h1(s-1)) ----
        uint32_t af[4][4], bf[4][4];
#pragma unroll
        for (int kc = 0; kc < 4; ++kc) {
            uint32_t colA = (((uint32_t)(kc * 32)) + aK2) ^ swz;
            ldsm4(A0r + aRow + colA, af[kc]);
            ldsm4(A1r + aRow + colA, bf[kc]);
        }

        float d0[2][2][4], da[2][2][4], db[2][2][4];
#pragma unroll
        for (int p = 0; p < 2; ++p)
#pragma unroll
            for (int u = 0; u < 2; ++u) {
                d0[p][u][0] = d0[p][u][1] = d0[p][u][2] = d0[p][u][3] = 0.f;
                da[p][u][0] = da[p][u][1] = da[p][u][2] = da[p][u][3] = 0.f;
                db[p][u][0] = db[p][u][1] = db[p][u][2] = db[p][u][3] = 0.f;
            }
        // ---- d0: h0(s) @ Whh0  (feeds epi-L0 below) ----
#pragma unroll
        for (int kc = 0; kc < 4; ++kc)
#pragma unroll
            for (int p = 0; p < 2; ++p) {
                mma_f16(d0[p][0], af[kc], f0[p][kc][0], f0[p][kc][1]);
                mma_f16(d0[p][1], af[kc], f0[p][kc][2], f0[p][kc][3]);
            }
        // ---- da: h0(s) @ Wih1 ----
#pragma unroll
        for (int kc = 0; kc < 4; ++kc)
#pragma unroll
            for (int p = 0; p < 2; ++p) {
                mma_f16(da[p][0], af[kc], f1a[p][kc][0], f1a[p][kc][1]);
                mma_f16(da[p][1], af[kc], f1a[p][kc][2], f1a[p][kc][3]);
            }

        // ---- epi L0(s+1): MUFU chains — scheduler overlaps db MMAs below ----
        {
            const int sn = (s + 1 < SEQ) ? (s + 1) : s;
            const float xi0 = xs[(sn & 31) * 16 + m0];
            const float xi1 = xs[(sn & 31) * 16 + m1];
#pragma unroll
            for (int p = 0; p < 2; ++p) {
                float h;
                h = cellup(d0[p][0][0], d0[p][0][1], d0[p][1][0], d0[p][1][1], b0a[p],
                           w0a[p][0]*xi0, w0a[p][1]*xi0, w0a[p][2]*xi0, w0a[p][3]*xi0,
                           c0[p][0]);
                *(__half*)(smem + (A0w - sb) + hoff[p]) = __float2half_rn(h);
                h = cellup(d0[p][0][2], d0[p][0][3], d0[p][1][2], d0[p][1][3], b0a[p],
                           w0a[p][0]*xi1, w0a[p][1]*xi1, w0a[p][2]*xi1, w0a[p][3]*xi1,
                           c0[p][1]);
                *(__half*)(smem + (A0w - sb) + hoff[p] + 1024) = __float2half_rn(h);
            }
        }

        // ---- db: h1(s-1) @ Whh1 (independent of epi L0 above) ----
#pragma unroll
        for (int kc = 0; kc < 4; ++kc)
#pragma unroll
            for (int p = 0; p < 2; ++p) {
                mma_f16(db[p][0], bf[kc], f1b[p][kc][0], f1b[p][kc][1]);
                mma_f16(db[p][1], bf[kc], f1b[p][kc][2], f1b[p][kc][3]);
            }

        // ---- epi L1(s): gates = da + db ----
#pragma unroll
        for (int p = 0; p < 2; ++p) {
            float h0v = cellup(da[p][0][0] + db[p][0][0], da[p][0][1] + db[p][0][1],
                               da[p][1][0] + db[p][1][0], da[p][1][1] + db[p][1][1],
                               b1a[p], 0.f, 0.f, 0.f, 0.f, c1[p][0]);
            float h1v = cellup(da[p][0][2] + db[p][0][2], da[p][0][3] + db[p][0][3],
                               da[p][1][2] + db[p][1][2], da[p][1][3] + db[p][1][3],
                               b1a[p], 0.f, 0.f, 0.f, 0.f, c1[p][1]);
            *(__half*)(smem + (A1w - sb) + hoff[p])        = __float2half_rn(h0v);
            *(__half*)(smem + (A1w - sb) + hoff[p] + 1024) = __float2half_rn(h1v);
            if (s == SEQ - 1) {
                ((float*)(smem + OFF_H1F))[m0 * 68 + ct[p]] = h0v;
                ((float*)(smem + OFF_H1F))[m1 * 68 + ct[p]] = h1v;
            }
        }
        __syncthreads();   // the one barrier: stores(s) visible before reads(s+1)
    }

    // ================= final FC: out = h1(S-1) @ fcw^T + fcb =================
    const float* h1f = (const float*)(smem + OFF_H1F);
    for (int idx = tid; idx < 16 * OUTF; idx += NTHR) {
        int r = idx / OUTF, o = idx - r * OUTF;
        float acc = fcb[o];
#pragma unroll 16
        for (int k = 0; k < 64; ++k)
            acc = fmaf(h1f[r * 68 + k], fcw[o * 64 + k], acc);
        out[(gRow + r) * OUTF + o] = acc;
    }
}

extern "C" void kernel_launch(void* const* d_in, const int* in_sizes, int n_in,
                              void* d_out, int out_size)
{
    (void)in_sizes; (void)n_in; (void)out_size;
    cudaFuncSetAttribute(lstm_mma_kernel,
                         cudaFuncAttributeMaxDynamicSharedMemorySize, SMEM_BYTES);
    lstm_mma_kernel<<<NCTA, NTHR, SMEM_BYTES>>>(
        (const float*)d_in[0],  (const float*)d_in[1],  (const float*)d_in[2],
        (const float*)d_in[3],  (const float*)d_in[4],  (const float*)d_in[5],
        (const float*)d_in[6],  (const float*)d_in[7],  (const float*)d_in[8],
        (const float*)d_in[9],  (const float*)d_in[10], (float*)d_out);
}

// round 15
// speedup vs baseline: 1.1835x; 1.0253x over previous
#include <cuda_runtime.h>
#include <cuda_fp16.h>
#include <cstdint>

#define SEQ  512
#define NTHR 256
#define NCTA 128
#define OUTF 72

// ---- SMEM map (bytes) ----
#define OFF_W0  0        // Whh0 fp16 [256 n''][64 k] SW128 (32KB)
#define OFF_W1  32768    // blk0=Wih1, blk1=Whh1 (+32768) (64KB)
#define OFF_A0  98304    // h0 fp16 tile [16 m][64 cell], 2 buffers x 2KB
#define OFF_A1  102400   // h1 fp16 tile, 2 buffers x 2KB
#define OFF_XS  106496   // x chunk [32 s][16 m] f32 (2KB)
#define OFF_H1F 108544   // h1 last, fp32 [16][68]
#define SMEM_BYTES 112896

#define SW128(o) ((o) ^ (((o) >> 3) & 0x70))

__device__ __forceinline__ uint32_t smem_u32(const void* p) {
    uint32_t a;
    asm("{ .reg .u64 t; cvta.to.shared.u64 t, %1; cvt.u32.u64 %0, t; }" : "=r"(a) : "l"(p));
    return a;
}
__device__ __forceinline__ void ldsm4(uint32_t addr, uint32_t r[4]) {
    asm volatile("ldmatrix.sync.aligned.m8n8.x4.shared.b16 {%0,%1,%2,%3}, [%4];"
                 : "=r"(r[0]), "=r"(r[1]), "=r"(r[2]), "=r"(r[3]) : "r"(addr));
}
__device__ __forceinline__ void mma_f16(float d[4], const uint32_t a[4],
                                        uint32_t b0, uint32_t b1) {
    asm("mma.sync.aligned.m16n8k16.row.col.f32.f16.f16.f32 "
        "{%0,%1,%2,%3}, {%4,%5,%6,%7}, {%8,%9}, {%0,%1,%2,%3};"
        : "+f"(d[0]), "+f"(d[1]), "+f"(d[2]), "+f"(d[3])
        : "r"(a[0]), "r"(a[1]), "r"(a[2]), "r"(a[3]), "r"(b0), "r"(b1));
}
__device__ __forceinline__ float tanha(float x) {
    float y; asm("tanh.approx.f32 %0, %1;" : "=f"(y) : "f"(x)); return y;
}
__device__ __forceinline__ __half2 th2(__half2 v) {
    uint32_t u = *reinterpret_cast<uint32_t*>(&v);
    asm("tanh.approx.f16x2 %0, %0;" : "+r"(u));
    return *reinterpret_cast<__half2*>(&u);
}

// Dual-row cell update. Gate pre-acts in f32 (sigmoid gates pre-scaled 0.5,
// biases/wx included). Gate tanhs in packed f16x2 (2 rows/op); c, tanh(c),
// and all gate algebra stay f32. Writes h for both rows.
__device__ __forceinline__ void cellup2(float vi0, float vf0, float vg0, float vo0,
                                        float vi1, float vf1, float vg1, float vo1,
                                        float* c, float& h0, float& h1)
{
    __half2 ti = th2(__floats2half2_rn(vi0, vi1));
    __half2 tf = th2(__floats2half2_rn(vf0, vf1));
    __half2 tg = th2(__floats2half2_rn(vg0, vg1));
    __half2 to = th2(__floats2half2_rn(vo0, vo1));
    float i0 = fmaf(__low2float(ti),  0.5f, 0.5f);
    float i1 = fmaf(__high2float(ti), 0.5f, 0.5f);
    float f0 = fmaf(__low2float(tf),  0.5f, 0.5f);
    float f1 = fmaf(__high2float(tf), 0.5f, 0.5f);
    float g0 = __low2float(tg),  g1 = __high2float(tg);
    float o0 = fmaf(__low2float(to),  0.5f, 0.5f);
    float o1 = fmaf(__high2float(to), 0.5f, 0.5f);
    c[0] = fmaf(f0, c[0], i0 * g0);
    c[1] = fmaf(f1, c[1], i1 * g1);
    h0 = o0 * tanha(c[0]);
    h1 = o1 * tanha(c[1]);
}

__global__ __launch_bounds__(NTHR, 1)
void lstm_mma_kernel(const float* __restrict__ x,
                     const float* __restrict__ Wih0, const float* __restrict__ Whh0,
                     const float* __restrict__ bih0, const float* __restrict__ bhh0,
                     const float* __restrict__ Wih1, const float* __restrict__ Whh1,
                     const float* __restrict__ bih1, const float* __restrict__ bhh1,
                     const float* __restrict__ fcw,  const float* __restrict__ fcb,
                     float* __restrict__ out)
{
    extern __shared__ char smem[];
    const uint32_t sb = smem_u32(smem);
    const int tid = threadIdx.x, warp = tid >> 5, lane = tid & 31;
    const int r8 = lane & 7, mid = lane >> 3;

    const uint32_t swz  = (uint32_t)(r8 << 4);
    const uint32_t aRow = (uint32_t)((r8 + ((mid & 1) << 3)) * 128);
    const uint32_t aK2  = (uint32_t)((mid & 2) << 3);
    const uint32_t bRow = (uint32_t)((r8 + ((mid & 2) << 2)) * 128);
    const uint32_t bK2  = (uint32_t)((mid & 1) << 4);

    // ---- weights -> SMEM, fp16, sigmoid rows pre-scaled by 0.5 (exact) ----
    // n'' = w*32 + pair*16 + gp*8 + c*2 + g2 : gate = gp*2+g2, cell = w*8+pair*4+c
    for (int idx = tid; idx < 256 * 64; idx += NTHR) {
        int np = idx >> 6, k = idx & 63;
        int gate = ((np >> 3) & 1) * 2 + (np & 1);
        int cell = (np >> 5) * 8 + ((np >> 4) & 1) * 4 + ((np >> 1) & 3);
        float sc = (gate == 2) ? 1.0f : 0.5f;
        uint32_t off = SW128((uint32_t)(np * 128 + k * 2));
        *(__half*)(smem + OFF_W0 + off) =
            __float2half_rn(sc * Whh0[(gate * 64 + cell) * 64 + k]);
    }
    for (int idx = tid; idx < 2 * 256 * 64; idx += NTHR) {
        int blk = idx >> 14, rem = idx & 16383;
        int np = rem >> 6, k = rem & 63;
        int gate = ((np >> 3) & 1) * 2 + (np & 1);
        int cell = (np >> 5) * 8 + ((np >> 4) & 1) * 4 + ((np >> 1) & 3);
        float sc = (gate == 2) ? 1.0f : 0.5f;
        float v = blk ? Whh1[(gate * 64 + cell) * 64 + k] : Wih1[(gate * 64 + cell) * 64 + k];
        uint32_t off = (uint32_t)(blk * 32768) + SW128((uint32_t)(np * 128 + k * 2));
        *(__half*)(smem + OFF_W1 + off) = __float2half_rn(sc * v);
    }
    for (int idx = tid; idx < 8192 / 4; idx += NTHR)
        ((uint32_t*)(smem + OFF_A0))[idx] = 0;

    // ---- per-lane assignment: 2 cells, 2 batch rows ----
    const int m0 = lane >> 2, m1 = m0 + 8;
    int ct[2];
    float b0a[2][4], w0a[2][4], b1a[2][4];
    uint32_t hoff[2];
#pragma unroll
    for (int p = 0; p < 2; ++p) {
        ct[p] = warp * 8 + p * 4 + (lane & 3);
#pragma unroll
        for (int g = 0; g < 4; ++g) {
            float sc = (g == 2) ? 1.0f : 0.5f;
            b0a[p][g] = sc * (bih0[g * 64 + ct[p]] + bhh0[g * 64 + ct[p]]);
            w0a[p][g] = sc * Wih0[g * 64 + ct[p]];
            b1a[p][g] = sc * (bih1[g * 64 + ct[p]] + bhh1[g * 64 + ct[p]]);
        }
        hoff[p] = (uint32_t)(m0 * 128 + ct[p] * 2) ^ (uint32_t)(m0 << 4);
    }
    float c0[2][2] = {{0.f, 0.f}, {0.f, 0.f}};
    float c1[2][2] = {{0.f, 0.f}, {0.f, 0.f}};

    float* xs = (float*)(smem + OFF_XS);
    const int gRow = blockIdx.x * 16;

    for (int q = tid; q < 512; q += NTHR)
        xs[q] = x[(size_t)(gRow + (q & 15)) * SEQ + (q >> 4)];
    __syncthreads();

    // ---- preload weight fragments ----
    uint32_t f0[2][4][4], f1a[2][4][4], f1b[2][4][4];
#pragma unroll
    for (int kc = 0; kc < 4; ++kc) {
        uint32_t colB = ((uint32_t)(kc * 32) + bK2) ^ swz;
#pragma unroll
        for (int p = 0; p < 2; ++p) {
            uint32_t base = (uint32_t)(warp * 4096 + p * 2048) + bRow + colB;
            ldsm4(sb + OFF_W0 + base, f0[p][kc]);
            ldsm4(sb + OFF_W1 + base, f1a[p][kc]);
            ldsm4(sb + OFF_W1 + 32768 + base, f1b[p][kc]);
        }
    }

    // ---- prologue: h0(0) = f(x(0)) -> A0 buf0 ----
    {
        const float xi0 = xs[m0], xi1 = xs[m1];
#pragma unroll
        for (int p = 0; p < 2; ++p) {
            float h0v, h1v;
            cellup2(w0a[p][0]*xi0 + b0a[p][0], w0a[p][1]*xi0 + b0a[p][1],
                    w0a[p][2]*xi0 + b0a[p][2], w0a[p][3]*xi0 + b0a[p][3],
                    w0a[p][0]*xi1 + b0a[p][0], w0a[p][1]*xi1 + b0a[p][1],
                    w0a[p][2]*xi1 + b0a[p][2], w0a[p][3]*xi1 + b0a[p][3],
                    c0[p], h0v, h1v);
            *(__half*)(smem + OFF_A0 + hoff[p])        = __float2half_rn(h0v);
            *(__half*)(smem + OFF_A0 + hoff[p] + 1024) = __float2half_rn(h1v);
        }
    }
    __syncthreads();

    // ================= main loop: ONE barrier per step =================
#pragma unroll 2
    for (int s = 0; s < SEQ; ++s) {
        if (((s + 1) & 31) == 0 && (s + 1) < SEQ) {
            for (int q = tid; q < 512; q += NTHR)
                xs[q] = x[(size_t)(gRow + (q & 15)) * SEQ + (s + 1) + (q >> 4)];
            __syncthreads();
        }
        const int rb = s & 1;
        const uint32_t A0r = sb + OFF_A0 + (uint32_t)(rb * 2048);
        const uint32_t A1r = sb + OFF_A1 + (uint32_t)(rb * 2048);
        const uint32_t A0w = sb + OFF_A0 + (uint32_t)((1 - rb) * 2048);
        const uint32_t A1w = sb + OFF_A1 + (uint32_t)((1 - rb) * 2048);

        uint32_t af[4][4], bf[4][4];
#pragma unroll
        for (int kc = 0; kc < 4; ++kc) {
            uint32_t colA = (((uint32_t)(kc * 32)) + aK2) ^ swz;
            ldsm4(A0r + aRow + colA, af[kc]);
            ldsm4(A1r + aRow + colA, bf[kc]);
        }

        float d0[2][2][4], d1[2][2][4];
#pragma unroll
        for (int p = 0; p < 2; ++p)
#pragma unroll
            for (int u = 0; u < 2; ++u) {
                d0[p][u][0] = d0[p][u][1] = d0[p][u][2] = d0[p][u][3] = 0.f;
                d1[p][u][0] = d1[p][u][1] = d1[p][u][2] = d1[p][u][3] = 0.f;
            }
        // ---- d0: h0(s) @ Whh0 ----
#pragma unroll
        for (int kc = 0; kc < 4; ++kc)
#pragma unroll
            for (int p = 0; p < 2; ++p) {
                mma_f16(d0[p][0], af[kc], f0[p][kc][0], f0[p][kc][1]);
                mma_f16(d0[p][1], af[kc], f0[p][kc][2], f0[p][kc][3]);
            }
        // ---- d1 += h0(s) @ Wih1 ----
#pragma unroll
        for (int kc = 0; kc < 4; ++kc)
#pragma unroll
            for (int p = 0; p < 2; ++p) {
                mma_f16(d1[p][0], af[kc], f1a[p][kc][0], f1a[p][kc][1]);
                mma_f16(d1[p][1], af[kc], f1a[p][kc][2], f1a[p][kc][3]);
            }

        // ---- epi L0(s+1): MUFU overlaps the d1/bf MMAs below ----
        {
            const int sn = (s + 1 < SEQ) ? (s + 1) : s;
            const float xi0 = xs[(sn & 31) * 16 + m0];
            const float xi1 = xs[(sn & 31) * 16 + m1];
#pragma unroll
            for (int p = 0; p < 2; ++p) {
                float h0v, h1v;
                cellup2(d0[p][0][0] + b0a[p][0] + w0a[p][0]*xi0,
                        d0[p][0][1] + b0a[p][1] + w0a[p][1]*xi0,
                        d0[p][1][0] + b0a[p][2] + w0a[p][2]*xi0,
                        d0[p][1][1] + b0a[p][3] + w0a[p][3]*xi0,
                        d0[p][0][2] + b0a[p][0] + w0a[p][0]*xi1,
                        d0[p][0][3] + b0a[p][1] + w0a[p][1]*xi1,
                        d0[p][1][2] + b0a[p][2] + w0a[p][2]*xi1,
                        d0[p][1][3] + b0a[p][3] + w0a[p][3]*xi1,
                        c0[p], h0v, h1v);
                *(__half*)(smem + (A0w - sb) + hoff[p])        = __float2half_rn(h0v);
                *(__half*)(smem + (A0w - sb) + hoff[p] + 1024) = __float2half_rn(h1v);
            }
        }

        // ---- d1 += h1(s-1) @ Whh1 (independent of epi-L0) ----
#pragma unroll
        for (int kc = 0; kc < 4; ++kc)
#pragma unroll
            for (int p = 0; p < 2; ++p) {
                mma_f16(d1[p][0], bf[kc], f1b[p][kc][0], f1b[p][kc][1]);
                mma_f16(d1[p][1], bf[kc], f1b[p][kc][2], f1b[p][kc][3]);
            }

        // ---- epi L1(s) ----
#pragma unroll
        for (int p = 0; p < 2; ++p) {
            float h0v, h1v;
            cellup2(d1[p][0][0] + b1a[p][0], d1[p][0][1] + b1a[p][1],
                    d1[p][1][0] + b1a[p][2], d1[p][1][1] + b1a[p][3],
                    d1[p][0][2] + b1a[p][0], d1[p][0][3] + b1a[p][1],
                    d1[p][1][2] + b1a[p][2], d1[p][1][3] + b1a[p][3],
                    c1[p], h0v, h1v);
            *(__half*)(smem + (A1w - sb) + hoff[p])        = __float2half_rn(h0v);
            *(__half*)(smem + (A1w - sb) + hoff[p] + 1024) = __float2half_rn(h1v);
            if (s == SEQ - 1) {
                ((float*)(smem + OFF_H1F))[m0 * 68 + ct[p]] = h0v;
                ((float*)(smem + OFF_H1F))[m1 * 68 + ct[p]] = h1v;
            }
        }
        __syncthreads();
    }

    // ================= final FC: out = h1(S-1) @ fcw^T + fcb =================
    const float* h1f = (const float*)(smem + OFF_H1F);
    for (int idx = tid; idx < 16 * OUTF; idx += NTHR) {
        int r = idx / OUTF, o = idx - r * OUTF;
        float acc = fcb[o];
#pragma unroll 16
        for (int k = 0; k < 64; ++k)
            acc = fmaf(h1f[r * 68 + k], fcw[o * 64 + k], acc);
        out[(gRow + r) * OUTF + o] = acc;
    }
}

extern "C" void kernel_launch(void* const* d_in, const int* in_sizes, int n_in,
                              void* d_out, int out_size)
{
    (void)in_sizes; (void)n_in; (void)out_size;
    cudaFuncSetAttribute(lstm_mma_kernel,
                         cudaFuncAttributeMaxDynamicSharedMemorySize, SMEM_BYTES);
    lstm_mma_kernel<<<NCTA, NTHR, SMEM_BYTES>>>(
        (const float*)d_in[0],  (const float*)d_in[1],  (const float*)d_in[2],
        (const float*)d_in[3],  (const float*)d_in[4],  (const float*)d_in[5],
        (const float*)d_in[6],  (const float*)d_in[7],  (const float*)d_in[8],
        (const float*)d_in[9],  (const float*)d_in[10], (float*)d_out);
}

// round 16
// speedup vs baseline: 1.1877x; 1.0036x over previous
#include <cuda_runtime.h>
#include <cuda_fp16.h>
#include <cstdint>

#define SEQ  512
#define NTHR 512
#define NCTA 128
#define OUTF 72

// ---- SMEM map (bytes) ----
#define OFF_W0  0        // Whh0 fp16 [256 n''][64 k] SW128 (32KB)
#define OFF_W1  32768    // blk0=Wih1, blk1=Whh1 (+32768) (64KB)
#define OFF_A0  98304    // h0 fp16 tile [16 m][64 cell], 2 buffers x 2KB
#define OFF_A1  102400   // h1 fp16 tile, 2 buffers x 2KB
#define OFF_XS  106496   // x chunk [32 s][16 m] f32 (2KB)
#define OFF_H1F 108544   // h1 last, fp32 [16][68]
#define SMEM_BYTES 112896

#define SW128(o) ((o) ^ (((o) >> 3) & 0x70))

__device__ __forceinline__ uint32_t smem_u32(const void* p) {
    uint32_t a;
    asm("{ .reg .u64 t; cvta.to.shared.u64 t, %1; cvt.u32.u64 %0, t; }" : "=r"(a) : "l"(p));
    return a;
}
__device__ __forceinline__ void ldsm4(uint32_t addr, uint32_t r[4]) {
    asm volatile("ldmatrix.sync.aligned.m8n8.x4.shared.b16 {%0,%1,%2,%3}, [%4];"
                 : "=r"(r[0]), "=r"(r[1]), "=r"(r[2]), "=r"(r[3]) : "r"(addr));
}
__device__ __forceinline__ void mma_f16(float d[4], const uint32_t a[4],
                                        uint32_t b0, uint32_t b1) {
    asm("mma.sync.aligned.m16n8k16.row.col.f32.f16.f16.f32 "
        "{%0,%1,%2,%3}, {%4,%5,%6,%7}, {%8,%9}, {%0,%1,%2,%3};"
        : "+f"(d[0]), "+f"(d[1]), "+f"(d[2]), "+f"(d[3])
        : "r"(a[0]), "r"(a[1]), "r"(a[2]), "r"(a[3]), "r"(b0), "r"(b1));
}
__device__ __forceinline__ float tanha(float x) {
    float y; asm("tanh.approx.f32 %0, %1;" : "=f"(y) : "f"(x)); return y;
}
__device__ __forceinline__ __half2 th2(__half2 v) {
    uint32_t u = *reinterpret_cast<uint32_t*>(&v);
    asm("tanh.approx.f16x2 %0, %0;" : "+r"(u));
    return *reinterpret_cast<__half2*>(&u);
}

// Dual-row cell update: gate tanhs packed f16x2 (2 rows/op); c, tanh(c) in f32.
__device__ __forceinline__ void cellup2(float vi0, float vf0, float vg0, float vo0,
                                        float vi1, float vf1, float vg1, float vo1,
                                        float* c, float& h0, float& h1)
{
    __half2 ti = th2(__floats2half2_rn(vi0, vi1));
    __half2 tf = th2(__floats2half2_rn(vf0, vf1));
    __half2 tg = th2(__floats2half2_rn(vg0, vg1));
    __half2 to = th2(__floats2half2_rn(vo0, vo1));
    float i0 = fmaf(__low2float(ti),  0.5f, 0.5f);
    float i1 = fmaf(__high2float(ti), 0.5f, 0.5f);
    float f0 = fmaf(__low2float(tf),  0.5f, 0.5f);
    float f1 = fmaf(__high2float(tf), 0.5f, 0.5f);
    float g0 = __low2float(tg),  g1 = __high2float(tg);
    float o0 = fmaf(__low2float(to),  0.5f, 0.5f);
    float o1 = fmaf(__high2float(to), 0.5f, 0.5f);
    c[0] = fmaf(f0, c[0], i0 * g0);
    c[1] = fmaf(f1, c[1], i1 * g1);
    h0 = o0 * tanha(c[0]);
    h1 = o1 * tanha(c[1]);
}

__global__ __launch_bounds__(NTHR, 1)
void lstm_mma_kernel(const float* __restrict__ x,
                     const float* __restrict__ Wih0, const float* __restrict__ Whh0,
                     const float* __restrict__ bih0, const float* __restrict__ bhh0,
                     const float* __restrict__ Wih1, const float* __restrict__ Whh1,
                     const float* __restrict__ bih1, const float* __restrict__ bhh1,
                     const float* __restrict__ fcw,  const float* __restrict__ fcb,
                     float* __restrict__ out)
{
    extern __shared__ char smem[];
    const uint32_t sb = smem_u32(smem);
    const int tid = threadIdx.x, warp = tid >> 5, lane = tid & 31;
    const int r8 = lane & 7, mid = lane >> 3;

    const uint32_t swz  = (uint32_t)(r8 << 4);
    const uint32_t aRow = (uint32_t)((r8 + ((mid & 1) << 3)) * 128);
    const uint32_t aK2  = (uint32_t)((mid & 2) << 3);
    const uint32_t bRow = (uint32_t)((r8 + ((mid & 2) << 2)) * 128);
    const uint32_t bK2  = (uint32_t)((mid & 1) << 4);

    // ---- weights -> SMEM, fp16, sigmoid rows pre-scaled by 0.5 (exact) ----
    // n'' = w*16 + gp*8 + c*2 + g2 : gate = gp*2+g2, cell = w*4+c  (w = warp 0..15)
    for (int idx = tid; idx < 256 * 64; idx += NTHR) {
        int np = idx >> 6, k = idx & 63;
        int gate = ((np >> 3) & 1) * 2 + (np & 1);
        int cell = (np >> 4) * 4 + ((np >> 1) & 3);
        float sc = (gate == 2) ? 1.0f : 0.5f;
        uint32_t off = SW128((uint32_t)(np * 128 + k * 2));
        *(__half*)(smem + OFF_W0 + off) =
            __float2half_rn(sc * Whh0[(gate * 64 + cell) * 64 + k]);
    }
    for (int idx = tid; idx < 2 * 256 * 64; idx += NTHR) {
        int blk = idx >> 14, rem = idx & 16383;
        int np = rem >> 6, k = rem & 63;
        int gate = ((np >> 3) & 1) * 2 + (np & 1);
        int cell = (np >> 4) * 4 + ((np >> 1) & 3);
        float sc = (gate == 2) ? 1.0f : 0.5f;
        float v = blk ? Whh1[(gate * 64 + cell) * 64 + k] : Wih1[(gate * 64 + cell) * 64 + k];
        uint32_t off = (uint32_t)(blk * 32768) + SW128((uint32_t)(np * 128 + k * 2));
        *(__half*)(smem + OFF_W1 + off) = __float2half_rn(sc * v);
    }
    for (int idx = tid; idx < 8192 / 4; idx += NTHR)
        ((uint32_t*)(smem + OFF_A0))[idx] = 0;

    // ---- per-lane assignment: ONE cell (warp's tile-pair), TWO batch rows ----
    const int m0 = lane >> 2, m1 = m0 + 8;
    const int ct = warp * 4 + (lane & 3);
    float b0a[4], w0a[4], b1a[4];
#pragma unroll
    for (int g = 0; g < 4; ++g) {
        float sc = (g == 2) ? 1.0f : 0.5f;
        b0a[g] = sc * (bih0[g * 64 + ct] + bhh0[g * 64 + ct]);
        w0a[g] = sc * Wih0[g * 64 + ct];
        b1a[g] = sc * (bih1[g * 64 + ct] + bhh1[g * 64 + ct]);
    }
    float c0[2] = {0.f, 0.f}, c1[2] = {0.f, 0.f};
    const uint32_t hoff = (uint32_t)(m0 * 128 + ct * 2) ^ (uint32_t)(m0 << 4);

    float* xs = (float*)(smem + OFF_XS);
    const int gRow = blockIdx.x * 16;

    if (tid < 512) xs[tid] = x[(size_t)(gRow + (tid & 15)) * SEQ + (tid >> 4)];
    __syncthreads();

    // ---- preload weight fragments (warp owns 16 n''-cols at base warp*2048) ----
    uint32_t f0[4][4], f1a[4][4], f1b[4][4];
#pragma unroll
    for (int kc = 0; kc < 4; ++kc) {
        uint32_t colB = ((uint32_t)(kc * 32) + bK2) ^ swz;
        uint32_t base = (uint32_t)(warp * 2048) + bRow + colB;
        ldsm4(sb + OFF_W0 + base, f0[kc]);
        ldsm4(sb + OFF_W1 + base, f1a[kc]);
        ldsm4(sb + OFF_W1 + 32768 + base, f1b[kc]);
    }

    // ---- prologue: h0(0) = f(x(0)) -> A0 buf0 ----
    {
        const float xi0 = xs[m0], xi1 = xs[m1];
        float h0v, h1v;
        cellup2(w0a[0]*xi0 + b0a[0], w0a[1]*xi0 + b0a[1],
                w0a[2]*xi0 + b0a[2], w0a[3]*xi0 + b0a[3],
                w0a[0]*xi1 + b0a[0], w0a[1]*xi1 + b0a[1],
                w0a[2]*xi1 + b0a[2], w0a[3]*xi1 + b0a[3], c0, h0v, h1v);
        *(__half*)(smem + OFF_A0 + hoff)        = __float2half_rn(h0v);
        *(__half*)(smem + OFF_A0 + hoff + 1024) = __float2half_rn(h1v);
    }
    __syncthreads();

    // ================= main loop: ONE barrier per step =================
#pragma unroll 2
    for (int s = 0; s < SEQ; ++s) {
        if (((s + 1) & 31) == 0 && (s + 1) < SEQ) {
            if (tid < 512)
                xs[tid] = x[(size_t)(gRow + (tid & 15)) * SEQ + (s + 1) + (tid >> 4)];
            __syncthreads();
        }
        const int rb = s & 1;
        const uint32_t A0r = sb + OFF_A0 + (uint32_t)(rb * 2048);
        const uint32_t A1r = sb + OFF_A1 + (uint32_t)(rb * 2048);
        const uint32_t A0w = sb + OFF_A0 + (uint32_t)((1 - rb) * 2048);
        const uint32_t A1w = sb + OFF_A1 + (uint32_t)((1 - rb) * 2048);

        // ---- af resident: one ldsm set, feeds d0 AND d1 ----
        uint32_t af[4][4];
#pragma unroll
        for (int kc = 0; kc < 4; ++kc)
            ldsm4(A0r + aRow + ((((uint32_t)(kc * 32)) + aK2) ^ swz), af[kc]);

        float d0[2][4], d1[2][4];
#pragma unroll
        for (int u = 0; u < 2; ++u) {
            d0[u][0] = d0[u][1] = d0[u][2] = d0[u][3] = 0.f;
            d1[u][0] = d1[u][1] = d1[u][2] = d1[u][3] = 0.f;
        }
        // ---- d0: h0(s) @ Whh0 ----
#pragma unroll
        for (int kc = 0; kc < 4; ++kc) {
            mma_f16(d0[0], af[kc], f0[kc][0], f0[kc][1]);
            mma_f16(d0[1], af[kc], f0[kc][2], f0[kc][3]);
        }
        // ---- d1 += h0(s) @ Wih1 ----
#pragma unroll
        for (int kc = 0; kc < 4; ++kc) {
            mma_f16(d1[0], af[kc], f1a[kc][0], f1a[kc][1]);
            mma_f16(d1[1], af[kc], f1a[kc][2], f1a[kc][3]);
        }

        // ---- epi L0(s+1): MUFU overlaps the d1/bf MMAs below ----
        {
            const int sn = (s + 1 < SEQ) ? (s + 1) : s;
            const float xi0 = xs[(sn & 31) * 16 + m0];
            const float xi1 = xs[(sn & 31) * 16 + m1];
            float h0v, h1v;
            cellup2(d0[0][0] + b0a[0] + w0a[0]*xi0, d0[0][1] + b0a[1] + w0a[1]*xi0,
                    d0[1][0] + b0a[2] + w0a[2]*xi0, d0[1][1] + b0a[3] + w0a[3]*xi0,
                    d0[0][2] + b0a[0] + w0a[0]*xi1, d0[0][3] + b0a[1] + w0a[1]*xi1,
                    d0[1][2] + b0a[2] + w0a[2]*xi1, d0[1][3] + b0a[3] + w0a[3]*xi1,
                    c0, h0v, h1v);
            *(__half*)(smem + (A0w - sb) + hoff)        = __float2half_rn(h0v);
            *(__half*)(smem + (A0w - sb) + hoff + 1024) = __float2half_rn(h1v);
        }

        // ---- d1 += h1(s-1) @ Whh1 (bf loaded per-kc; independent of epi-L0) ----
#pragma unroll
        for (int kc = 0; kc < 4; ++kc) {
            uint32_t bf[4];
            ldsm4(A1r + aRow + ((((uint32_t)(kc * 32)) + aK2) ^ swz), bf);
            mma_f16(d1[0], bf, f1b[kc][0], f1b[kc][1]);
            mma_f16(d1[1], bf, f1b[kc][2], f1b[kc][3]);
        }

        // ---- epi L1(s) ----
        {
            float h0v, h1v;
            cellup2(d1[0][0] + b1a[0], d1[0][1] + b1a[1],
                    d1[1][0] + b1a[2], d1[1][1] + b1a[3],
                    d1[0][2] + b1a[0], d1[0][3] + b1a[1],
                    d1[1][2] + b1a[2], d1[1][3] + b1a[3], c1, h0v, h1v);
            *(__half*)(smem + (A1w - sb) + hoff)        = __float2half_rn(h0v);
            *(__half*)(smem + (A1w - sb) + hoff + 1024) = __float2half_rn(h1v);
            if (s == SEQ - 1) {
                ((float*)(smem + OFF_H1F))[m0 * 68 + ct] = h0v;
                ((float*)(smem + OFF_H1F))[m1 * 68 + ct] = h1v;
            }
        }
        __syncthreads();
    }

    // ================= final FC: out = h1(S-1) @ fcw^T + fcb =================
    const float* h1f = (const float*)(smem + OFF_H1F);
    for (int idx = tid; idx < 16 * OUTF; idx += NTHR) {
        int r = idx / OUTF, o = idx - r * OUTF;
        float acc = fcb[o];
#pragma unroll 16
        for (int k = 0; k < 64; ++k)
            acc = fmaf(h1f[r * 68 + k], fcw[o * 64 + k], acc);
        out[(gRow + r) * OUTF + o] = acc;
    }
}

extern "C" void kernel_launch(void* const* d_in, const int* in_sizes, int n_in,
                              void* d_out, int out_size)
{
    (void)in_sizes; (void)n_in; (void)out_size;
    cudaFuncSetAttribute(lstm_mma_kernel,
                         cudaFuncAttributeMaxDynamicSharedMemorySize, SMEM_BYTES);
    lstm_mma_kernel<<<NCTA, NTHR, SMEM_BYTES>>>(
        (const float*)d_in[0],  (const float*)d_in[1],  (const float*)d_in[2],
        (const float*)d_in[3],  (const float*)d_in[4],  (const float*)d_in[5],
        (const float*)d_in[6],  (const float*)d_in[7],  (const float*)d_in[8],
        (const float*)d_in[9],  (const float*)d_in[10], (float*)d_out);
}